// round 1
// baseline (speedup 1.0000x reference)
#include <cuda_runtime.h>
#include <math_constants.h>

// Problem constants
#define B_    2
#define T_    2048
#define C_    1024
#define H_    16
#define D_    64
#define M_    (B_ * T_)      // 4096 rows
#define QKVN  (3 * C_)       // 3072

// Scratch (device globals: allocation-free per harness rules)
__device__ float g_qkv[(size_t)M_ * QKVN];   // [B*T, 3C]  (q | k | v per row)
__device__ float g_att[(size_t)M_ * C_];     // [B*T, C]   attention output

// ---------------------------------------------------------------------------
// GEMM (NT): C[M,N] = A[M,K] @ B[N,K]^T.  Both operands K-contiguous.
// 128x128 tile, BK=16, 256 threads, 8x8 per thread, float4 everywhere.
// ---------------------------------------------------------------------------
__global__ __launch_bounds__(256)
void gemm_nt_kernel(const float* __restrict__ A,
                    const float* __restrict__ Bm,
                    float* __restrict__ Cm,
                    int M, int N, int K)
{
    constexpr int BM = 128, BN = 128, BK = 16;
    __shared__ float As[BK][BM];   // transposed: As[k][m]
    __shared__ float Bs[BK][BN];   // transposed: Bs[k][n]

    const int tid = threadIdx.x;
    const int tn  = tid & 15;      // 0..15 -> n sub-block of 8
    const int tm  = tid >> 4;      // 0..15 -> m sub-block of 8
    const int m0  = blockIdx.y * BM;
    const int n0  = blockIdx.x * BN;

    const int lr = tid >> 2;          // 0..63  row within tile (2 passes)
    const int lc = (tid & 3) << 2;    // 0,4,8,12 k-column

    float acc[8][8];
#pragma unroll
    for (int i = 0; i < 8; i++)
#pragma unroll
        for (int j = 0; j < 8; j++) acc[i][j] = 0.f;

    for (int k0 = 0; k0 < K; k0 += BK) {
#pragma unroll
        for (int p = 0; p < 2; p++) {
            const int row = lr + p * 64;
            float4 av = *(const float4*)(A  + (size_t)(m0 + row) * K + k0 + lc);
            As[lc + 0][row] = av.x; As[lc + 1][row] = av.y;
            As[lc + 2][row] = av.z; As[lc + 3][row] = av.w;
            float4 bv = *(const float4*)(Bm + (size_t)(n0 + row) * K + k0 + lc);
            Bs[lc + 0][row] = bv.x; Bs[lc + 1][row] = bv.y;
            Bs[lc + 2][row] = bv.z; Bs[lc + 3][row] = bv.w;
        }
        __syncthreads();

#pragma unroll
        for (int kk = 0; kk < BK; kk++) {
            float a[8], b[8];
            *(float4*)&a[0] = *(const float4*)&As[kk][tm * 8];
            *(float4*)&a[4] = *(const float4*)&As[kk][tm * 8 + 4];
            *(float4*)&b[0] = *(const float4*)&Bs[kk][tn * 8];
            *(float4*)&b[4] = *(const float4*)&Bs[kk][tn * 8 + 4];
#pragma unroll
            for (int i = 0; i < 8; i++)
#pragma unroll
                for (int j = 0; j < 8; j++)
                    acc[i][j] = fmaf(a[i], b[j], acc[i][j]);
        }
        __syncthreads();
    }

#pragma unroll
    for (int i = 0; i < 8; i++) {
        const size_t off = (size_t)(m0 + tm * 8 + i) * N + n0 + tn * 8;
        *(float4*)(Cm + off)     = make_float4(acc[i][0], acc[i][1], acc[i][2], acc[i][3]);
        *(float4*)(Cm + off + 4) = make_float4(acc[i][4], acc[i][5], acc[i][6], acc[i][7]);
    }
}

// ---------------------------------------------------------------------------
// Flash attention (fp32, causal). One block per (q-tile of 64, head, batch).
// K/V tiles of 32 rows. Online softmax in registers.
// Thread map: tn = tid&7 (k-cols x4 in S, d-cols x8 in PV), tm = tid>>3 (2 q rows).
// ---------------------------------------------------------------------------
__global__ __launch_bounds__(256)
void attn_kernel(const float* __restrict__ qkv, float* __restrict__ att)
{
    constexpr int BQ = 64, BKV = 32;
    __shared__ float Qs[D_][BQ];        // transposed Q: Qs[d][q]      16 KB
    __shared__ float Ks[D_][BKV];       // transposed+swizzled K        8 KB
    __shared__ float Vs[BKV][D_];       // natural V                    8 KB
    __shared__ float Ps[BQ][BKV + 1];   // P tile (pad 33)           8.25 KB

    const int qb = blockIdx.x, h = blockIdx.y, b = blockIdx.z;
    const int q0 = qb * BQ;
    const int tid = threadIdx.x;
    const int tn  = tid & 7;    // 0..7
    const int tm  = tid >> 3;   // 0..31
    const int d4  = tid & 15;   // 0..15 (loaders)
    const int r16 = tid >> 4;   // 0..15 (loaders)

    // ---- load Q tile, transposed into smem (once per block) ----
    const float* qbase = qkv + ((size_t)(b * T_ + q0)) * QKVN + h * D_;
#pragma unroll
    for (int p = 0; p < 4; p++) {
        const int row = r16 + p * 16;
        float4 v = *(const float4*)(qbase + (size_t)row * QKVN + d4 * 4);
        Qs[d4 * 4 + 0][row] = v.x; Qs[d4 * 4 + 1][row] = v.y;
        Qs[d4 * 4 + 2][row] = v.z; Qs[d4 * 4 + 3][row] = v.w;
    }
    __syncthreads();

    float m_[2] = { -CUDART_INF_F, -CUDART_INF_F };
    float l_[2] = { 0.f, 0.f };
    float o_[2][8];
#pragma unroll
    for (int i = 0; i < 2; i++)
#pragma unroll
        for (int j = 0; j < 8; j++) o_[i][j] = 0.f;

    const int nkb = 2 * qb + 2;   // causal: only tiles with k0 <= q0+63
    for (int kb = 0; kb < nkb; kb++) {
        const int k0 = kb * BKV;
        const float* kbase = qkv + ((size_t)(b * T_ + k0)) * QKVN + C_     + h * D_;
        const float* vbase = qkv + ((size_t)(b * T_ + k0)) * QKVN + 2 * C_ + h * D_;

        // ---- load K (transposed + swizzled) and V (natural) ----
#pragma unroll
        for (int p = 0; p < 2; p++) {
            const int krow = r16 + p * 16;                     // 0..31
            float4 kv = *(const float4*)(kbase + (size_t)krow * QKVN + d4 * 4);
            const int col = ((((krow >> 2) ^ (d4 & 7)) << 2) | (krow & 3));
            Ks[d4 * 4 + 0][col] = kv.x; Ks[d4 * 4 + 1][col] = kv.y;
            Ks[d4 * 4 + 2][col] = kv.z; Ks[d4 * 4 + 3][col] = kv.w;
            float4 vv = *(const float4*)(vbase + (size_t)krow * QKVN + d4 * 4);
            *(float4*)&Vs[krow][d4 * 4] = vv;
        }
        __syncthreads();

        // ---- S = Q @ K^T  (64x32 tile; thread owns 2 q-rows x 4 k-cols) ----
        float s_[2][4];
#pragma unroll
        for (int i = 0; i < 2; i++)
#pragma unroll
            for (int j = 0; j < 4; j++) s_[i][j] = 0.f;

#pragma unroll
        for (int d = 0; d < D_; d++) {
            const float2 a  = *(const float2*)&Qs[d][tm * 2];
            const float4 kv = *(const float4*)&Ks[d][((tn ^ ((d >> 2) & 7)) << 2)];
            s_[0][0] = fmaf(a.x, kv.x, s_[0][0]);
            s_[0][1] = fmaf(a.x, kv.y, s_[0][1]);
            s_[0][2] = fmaf(a.x, kv.z, s_[0][2]);
            s_[0][3] = fmaf(a.x, kv.w, s_[0][3]);
            s_[1][0] = fmaf(a.y, kv.x, s_[1][0]);
            s_[1][1] = fmaf(a.y, kv.y, s_[1][1]);
            s_[1][2] = fmaf(a.y, kv.z, s_[1][2]);
            s_[1][3] = fmaf(a.y, kv.w, s_[1][3]);
        }

        // ---- causal mask + online softmax (row stats across 8 lanes) ----
#pragma unroll
        for (int i = 0; i < 2; i++) {
            const int qg = q0 + tm * 2 + i;
            float rmax = -CUDART_INF_F;
#pragma unroll
            for (int j = 0; j < 4; j++) {
                const int kg = k0 + tn * 4 + j;
                float sv = (kg <= qg) ? s_[i][j] * 0.125f : -CUDART_INF_F;
                s_[i][j] = sv;
                rmax = fmaxf(rmax, sv);
            }
            rmax = fmaxf(rmax, __shfl_xor_sync(0xffffffffu, rmax, 1, 8));
            rmax = fmaxf(rmax, __shfl_xor_sync(0xffffffffu, rmax, 2, 8));
            rmax = fmaxf(rmax, __shfl_xor_sync(0xffffffffu, rmax, 4, 8));
            const float mnew  = fmaxf(m_[i], rmax);
            const float alpha = __expf(m_[i] - mnew);
            float rsum = 0.f;
#pragma unroll
            for (int j = 0; j < 4; j++) {
                const float p = __expf(s_[i][j] - mnew);
                Ps[tm * 2 + i][tn * 4 + j] = p;
                rsum += p;
            }
            rsum += __shfl_xor_sync(0xffffffffu, rsum, 1, 8);
            rsum += __shfl_xor_sync(0xffffffffu, rsum, 2, 8);
            rsum += __shfl_xor_sync(0xffffffffu, rsum, 4, 8);
            l_[i] = l_[i] * alpha + rsum;
            m_[i] = mnew;
#pragma unroll
            for (int j = 0; j < 8; j++) o_[i][j] *= alpha;
        }
        __syncthreads();

        // ---- O += P @ V  (thread owns 2 q-rows x 8 d-cols) ----
#pragma unroll
        for (int kk = 0; kk < BKV; kk++) {
            const float p0 = Ps[tm * 2][kk];
            const float p1 = Ps[tm * 2 + 1][kk];
            const float4 v0 = *(const float4*)&Vs[kk][tn * 8];
            const float4 v1 = *(const float4*)&Vs[kk][tn * 8 + 4];
            o_[0][0] = fmaf(p0, v0.x, o_[0][0]);
            o_[0][1] = fmaf(p0, v0.y, o_[0][1]);
            o_[0][2] = fmaf(p0, v0.z, o_[0][2]);
            o_[0][3] = fmaf(p0, v0.w, o_[0][3]);
            o_[0][4] = fmaf(p0, v1.x, o_[0][4]);
            o_[0][5] = fmaf(p0, v1.y, o_[0][5]);
            o_[0][6] = fmaf(p0, v1.z, o_[0][6]);
            o_[0][7] = fmaf(p0, v1.w, o_[0][7]);
            o_[1][0] = fmaf(p1, v0.x, o_[1][0]);
            o_[1][1] = fmaf(p1, v0.y, o_[1][1]);
            o_[1][2] = fmaf(p1, v0.z, o_[1][2]);
            o_[1][3] = fmaf(p1, v0.w, o_[1][3]);
            o_[1][4] = fmaf(p1, v1.x, o_[1][4]);
            o_[1][5] = fmaf(p1, v1.y, o_[1][5]);
            o_[1][6] = fmaf(p1, v1.z, o_[1][6]);
            o_[1][7] = fmaf(p1, v1.w, o_[1][7]);
        }
        __syncthreads();
    }

    // ---- epilogue: normalize and write [B,T,C] layout ----
#pragma unroll
    for (int i = 0; i < 2; i++) {
        const float inv = 1.f / l_[i];
        float* dst = att + ((size_t)(b * T_ + q0 + tm * 2 + i)) * C_ + h * D_ + tn * 8;
        *(float4*)dst       = make_float4(o_[i][0] * inv, o_[i][1] * inv,
                                          o_[i][2] * inv, o_[i][3] * inv);
        *(float4*)(dst + 4) = make_float4(o_[i][4] * inv, o_[i][5] * inv,
                                          o_[i][6] * inv, o_[i][7] * inv);
    }
}

// ---------------------------------------------------------------------------
extern "C" void kernel_launch(void* const* d_in, const int* in_sizes, int n_in,
                              void* d_out, int out_size)
{
    (void)in_sizes; (void)n_in; (void)out_size;
    const float* x     = (const float*)d_in[0];   // [B,T,C]
    const float* wqkv  = (const float*)d_in[1];   // [3C,C]
    const float* wproj = (const float*)d_in[2];   // [C,C]
    float* out = (float*)d_out;                   // [B,T,C]

    float* qkv = nullptr;
    float* att = nullptr;
    cudaGetSymbolAddress((void**)&qkv, g_qkv);
    cudaGetSymbolAddress((void**)&att, g_att);

    dim3 blk(256);
    // 1) QKV projection: [4096,3072] = x @ w_qkv^T
    gemm_nt_kernel<<<dim3(QKVN / 128, M_ / 128), blk>>>(x, wqkv, qkv, M_, QKVN, C_);
    // 2) causal attention -> g_att [4096,1024]
    attn_kernel<<<dim3(T_ / 64, H_, B_), blk>>>(qkv, att);
    // 3) output projection: out = g_att @ w_proj^T
    gemm_nt_kernel<<<dim3(C_ / 128, M_ / 128), blk>>>(att, wproj, out, M_, C_, C_);
}

// round 3
// speedup vs baseline: 1.3364x; 1.3364x over previous
#include <cuda_runtime.h>
#include <cuda_bf16.h>
#include <math_constants.h>
#include <cstdint>

// Problem constants
#define B_    2
#define T_    2048
#define C_    1024
#define H_    16
#define D_    64
#define M_    (B_ * T_)      // 4096
#define QKVN  (3 * C_)       // 3072
#define K_    1024

// ---------------------------------------------------------------------------
// Device scratch
// ---------------------------------------------------------------------------
__device__ float g_qkv[(size_t)M_ * QKVN];
__device__ float g_att[(size_t)M_ * C_];

__device__ __nv_bfloat16 s_xh[(size_t)M_ * C_];
__device__ __nv_bfloat16 s_xl[(size_t)M_ * C_];
__device__ __nv_bfloat16 s_wqh[(size_t)QKVN * C_];
__device__ __nv_bfloat16 s_wql[(size_t)QKVN * C_];
__device__ __nv_bfloat16 s_ah[(size_t)M_ * C_];
__device__ __nv_bfloat16 s_al[(size_t)M_ * C_];
__device__ __nv_bfloat16 s_wph[(size_t)C_ * C_];
__device__ __nv_bfloat16 s_wpl[(size_t)C_ * C_];

// ---------------------------------------------------------------------------
// PTX helpers (portable: cp.async + ldmatrix + mma.sync only)
// ---------------------------------------------------------------------------
__device__ __forceinline__ uint32_t smem_u32(const void* p) {
    uint32_t a;
    asm("{ .reg .u64 t; cvta.to.shared.u64 t, %1; cvt.u32.u64 %0, t; }"
        : "=r"(a) : "l"(p));
    return a;
}

#define CP_ASYNC_16(dst, src) \
    asm volatile("cp.async.cg.shared.global [%0], [%1], 16;" \
                 :: "r"(dst), "l"(src) : "memory")
#define CP_ASYNC_COMMIT() asm volatile("cp.async.commit_group;" ::: "memory")
#define CP_ASYNC_WAIT_1() asm volatile("cp.async.wait_group 1;" ::: "memory")
#define CP_ASYNC_WAIT_0() asm volatile("cp.async.wait_group 0;" ::: "memory")

__device__ __forceinline__ void ldm_x4(uint32_t& r0, uint32_t& r1,
                                       uint32_t& r2, uint32_t& r3, uint32_t a) {
    asm volatile("ldmatrix.sync.aligned.m8n8.x4.shared.b16 {%0,%1,%2,%3}, [%4];"
                 : "=r"(r0), "=r"(r1), "=r"(r2), "=r"(r3) : "r"(a));
}

__device__ __forceinline__ void mma16816(float* c, const uint32_t* a,
                                         const uint32_t* b) {
    asm volatile(
        "mma.sync.aligned.m16n8k16.row.col.f32.bf16.bf16.f32 "
        "{%0,%1,%2,%3}, {%4,%5,%6,%7}, {%8,%9}, {%0,%1,%2,%3};"
        : "+f"(c[0]), "+f"(c[1]), "+f"(c[2]), "+f"(c[3])
        : "r"(a[0]), "r"(a[1]), "r"(a[2]), "r"(a[3]), "r"(b[0]), "r"(b[1]));
}

// ---------------------------------------------------------------------------
// bf16 hi/lo split
// ---------------------------------------------------------------------------
__global__ __launch_bounds__(256)
void split_bf16_kernel(const float* __restrict__ in,
                       __nv_bfloat16* __restrict__ hi,
                       __nv_bfloat16* __restrict__ lo, int n2)
{
    int i = blockIdx.x * blockDim.x + threadIdx.x;
    if (i >= n2) return;
    float2 v = ((const float2*)in)[i];
    __nv_bfloat16 hx = __float2bfloat16_rn(v.x);
    __nv_bfloat16 hy = __float2bfloat16_rn(v.y);
    __nv_bfloat16 lx = __float2bfloat16_rn(v.x - __bfloat162float(hx));
    __nv_bfloat16 ly = __float2bfloat16_rn(v.y - __bfloat162float(hy));
    __nv_bfloat162 h2; h2.x = hx; h2.y = hy;
    __nv_bfloat162 l2; l2.x = lx; l2.y = ly;
    ((__nv_bfloat162*)hi)[i] = h2;
    ((__nv_bfloat162*)lo)[i] = l2;
}

// ---------------------------------------------------------------------------
// mma.sync bf16 split-GEMM: C[M,N](fp32) = (Ah+Al)[M,K] @ (Bh+Bl)[N,K]^T
// 3 passes (hh, lh, hl) accumulated in fp32 registers.
// 128x128 tile, BK=64 (128B rows, XOR swizzle), 256 thr = 8 warps (2m x 4n),
// warp tile 64x32, 2-stage cp.async pipeline.
// ---------------------------------------------------------------------------
#define KT_   (K_ / 64)      // 16 k-tiles per pass
#define NIT_  (3 * KT_)      // 48
#define TILEB 16384          // one operand stage: 128 rows * 128B
#define GEMM_SMEM (4 * TILEB + 128)

__device__ __forceinline__ void issue_tile_load(
    int L,
    const __nv_bfloat16* __restrict__ Ah, const __nv_bfloat16* __restrict__ Al,
    const __nv_bfloat16* __restrict__ Bh, const __nv_bfloat16* __restrict__ Bl,
    uint32_t sA, uint32_t sB, int m0, int n0, int tid)
{
    const int p  = L >> 4;
    const int kt = L & 15;
    const __nv_bfloat16* A = (p == 1) ? Al : Ah;
    const __nv_bfloat16* B = (p == 2) ? Bl : Bh;
    const int r0 = tid >> 3;           // 0..31
    const int ch = tid & 7;            // 16B chunk
    const uint32_t cb = (uint32_t)ch * 16u;
#pragma unroll
    for (int q = 0; q < 4; q++) {
        const int row = r0 + q * 32;
        const uint32_t sw = (uint32_t)row * 128u + (cb ^ (((uint32_t)row & 7u) << 4));
        CP_ASYNC_16(sA + sw, A + (size_t)(m0 + row) * K_ + kt * 64 + ch * 8);
        CP_ASYNC_16(sB + sw, B + (size_t)(n0 + row) * K_ + kt * 64 + ch * 8);
    }
    CP_ASYNC_COMMIT();
}

__global__ __launch_bounds__(256)
void gemm_bf16_split_kernel(const __nv_bfloat16* __restrict__ Ah,
                            const __nv_bfloat16* __restrict__ Al,
                            const __nv_bfloat16* __restrict__ Bh,
                            const __nv_bfloat16* __restrict__ Bl,
                            float* __restrict__ Cm, int N)
{
    extern __shared__ char dsm[];
    const uint32_t base = (smem_u32(dsm) + 127u) & ~127u;

    const int tid  = threadIdx.x;
    const int wid  = tid >> 5;
    const int lane = tid & 31;
    const int wm   = wid >> 2;          // 0..1
    const int wn   = wid & 3;           // 0..3
    const int m0 = blockIdx.y * 128;
    const int n0 = blockIdx.x * 128;

    const uint32_t sA[2] = { base,             base + 2 * TILEB };
    const uint32_t sB[2] = { base + TILEB,     base + 3 * TILEB };

    float acc[4][4][4];
#pragma unroll
    for (int i = 0; i < 4; i++)
#pragma unroll
        for (int j = 0; j < 4; j++)
#pragma unroll
            for (int q = 0; q < 4; q++) acc[i][j][q] = 0.f;

    // ldmatrix lane addressing: 16 rows + 16B column select
    const int lr = lane & 15;
    const uint32_t lc = ((uint32_t)(lane >> 4)) << 4;

    issue_tile_load(0, Ah, Al, Bh, Bl, sA[0], sB[0], m0, n0, tid);
    issue_tile_load(1, Ah, Al, Bh, Bl, sA[1], sB[1], m0, n0, tid);

    for (int it = 0; it < NIT_; ++it) {
        const int s = it & 1;
        if (it + 2 < NIT_) { CP_ASYNC_WAIT_1(); } else { CP_ASYNC_WAIT_0(); }
        __syncthreads();

        // compute stage s: 4 k-steps of 16
#pragma unroll
        for (int kk = 0; kk < 4; kk++) {
            const uint32_t colb = (uint32_t)kk * 32u + lc;
            uint32_t a[4][4];
#pragma unroll
            for (int mi = 0; mi < 4; mi++) {
                const int row = wm * 64 + mi * 16 + lr;
                const uint32_t ad = sA[s] + (uint32_t)row * 128u +
                                    (colb ^ (((uint32_t)row & 7u) << 4));
                ldm_x4(a[mi][0], a[mi][1], a[mi][2], a[mi][3], ad);
            }
            uint32_t b[4][2];
#pragma unroll
            for (int bj = 0; bj < 2; bj++) {
                const int row = wn * 32 + bj * 16 + lr;
                const uint32_t ad = sB[s] + (uint32_t)row * 128u +
                                    (colb ^ (((uint32_t)row & 7u) << 4));
                uint32_t r0, r1, r2, r3;
                ldm_x4(r0, r1, r2, r3, ad);
                b[bj * 2 + 0][0] = r0; b[bj * 2 + 1][0] = r1;
                b[bj * 2 + 0][1] = r2; b[bj * 2 + 1][1] = r3;
            }
#pragma unroll
            for (int mi = 0; mi < 4; mi++)
#pragma unroll
                for (int ni = 0; ni < 4; ni++)
                    mma16816(acc[mi][ni], a[mi], b[ni]);
        }
        __syncthreads();

        if (it + 2 < NIT_)
            issue_tile_load(it + 2, Ah, Al, Bh, Bl, sA[s], sB[s], m0, n0, tid);
    }

    // epilogue: fp32 accumulators -> global
    const int rr = lane >> 2;
    const int cc = (lane & 3) * 2;
#pragma unroll
    for (int mi = 0; mi < 4; mi++) {
#pragma unroll
        for (int ni = 0; ni < 4; ni++) {
            const int gm = m0 + wm * 64 + mi * 16 + rr;
            const int gn = n0 + wn * 32 + ni * 8 + cc;
            *(float2*)(Cm + (size_t)gm * N + gn) =
                make_float2(acc[mi][ni][0], acc[mi][ni][1]);
            *(float2*)(Cm + (size_t)(gm + 8) * N + gn) =
                make_float2(acc[mi][ni][2], acc[mi][ni][3]);
        }
    }
}

// ---------------------------------------------------------------------------
// Flash attention (fp32, causal) — unchanged (proven, round 1).
// ---------------------------------------------------------------------------
__global__ __launch_bounds__(256)
void attn_kernel(const float* __restrict__ qkv, float* __restrict__ att)
{
    constexpr int BQ = 64, BKV = 32;
    __shared__ float Qs[D_][BQ];
    __shared__ float Ks[D_][BKV];
    __shared__ float Vs[BKV][D_];
    __shared__ float Ps[BQ][BKV + 1];

    const int qb = blockIdx.x, h = blockIdx.y, b = blockIdx.z;
    const int q0 = qb * BQ;
    const int tid = threadIdx.x;
    const int tn  = tid & 7;
    const int tm  = tid >> 3;
    const int d4  = tid & 15;
    const int r16 = tid >> 4;

    const float* qbase = qkv + ((size_t)(b * T_ + q0)) * QKVN + h * D_;
#pragma unroll
    for (int p = 0; p < 4; p++) {
        const int row = r16 + p * 16;
        float4 v = *(const float4*)(qbase + (size_t)row * QKVN + d4 * 4);
        Qs[d4 * 4 + 0][row] = v.x; Qs[d4 * 4 + 1][row] = v.y;
        Qs[d4 * 4 + 2][row] = v.z; Qs[d4 * 4 + 3][row] = v.w;
    }
    __syncthreads();

    float m_[2] = { -CUDART_INF_F, -CUDART_INF_F };
    float l_[2] = { 0.f, 0.f };
    float o_[2][8];
#pragma unroll
    for (int i = 0; i < 2; i++)
#pragma unroll
        for (int j = 0; j < 8; j++) o_[i][j] = 0.f;

    const int nkb = 2 * qb + 2;
    for (int kb = 0; kb < nkb; kb++) {
        const int k0 = kb * BKV;
        const float* kbase = qkv + ((size_t)(b * T_ + k0)) * QKVN + C_     + h * D_;
        const float* vbase = qkv + ((size_t)(b * T_ + k0)) * QKVN + 2 * C_ + h * D_;

#pragma unroll
        for (int p = 0; p < 2; p++) {
            const int krow = r16 + p * 16;
            float4 kv = *(const float4*)(kbase + (size_t)krow * QKVN + d4 * 4);
            const int col = ((((krow >> 2) ^ (d4 & 7)) << 2) | (krow & 3));
            Ks[d4 * 4 + 0][col] = kv.x; Ks[d4 * 4 + 1][col] = kv.y;
            Ks[d4 * 4 + 2][col] = kv.z; Ks[d4 * 4 + 3][col] = kv.w;
            float4 vv = *(const float4*)(vbase + (size_t)krow * QKVN + d4 * 4);
            *(float4*)&Vs[krow][d4 * 4] = vv;
        }
        __syncthreads();

        float s_[2][4];
#pragma unroll
        for (int i = 0; i < 2; i++)
#pragma unroll
            for (int j = 0; j < 4; j++) s_[i][j] = 0.f;

#pragma unroll
        for (int d = 0; d < D_; d++) {
            const float2 a  = *(const float2*)&Qs[d][tm * 2];
            const float4 kv = *(const float4*)&Ks[d][((tn ^ ((d >> 2) & 7)) << 2)];
            s_[0][0] = fmaf(a.x, kv.x, s_[0][0]);
            s_[0][1] = fmaf(a.x, kv.y, s_[0][1]);
            s_[0][2] = fmaf(a.x, kv.z, s_[0][2]);
            s_[0][3] = fmaf(a.x, kv.w, s_[0][3]);
            s_[1][0] = fmaf(a.y, kv.x, s_[1][0]);
            s_[1][1] = fmaf(a.y, kv.y, s_[1][1]);
            s_[1][2] = fmaf(a.y, kv.z, s_[1][2]);
            s_[1][3] = fmaf(a.y, kv.w, s_[1][3]);
        }

#pragma unroll
        for (int i = 0; i < 2; i++) {
            const int qg = q0 + tm * 2 + i;
            float rmax = -CUDART_INF_F;
#pragma unroll
            for (int j = 0; j < 4; j++) {
                const int kg = k0 + tn * 4 + j;
                float sv = (kg <= qg) ? s_[i][j] * 0.125f : -CUDART_INF_F;
                s_[i][j] = sv;
                rmax = fmaxf(rmax, sv);
            }
            rmax = fmaxf(rmax, __shfl_xor_sync(0xffffffffu, rmax, 1, 8));
            rmax = fmaxf(rmax, __shfl_xor_sync(0xffffffffu, rmax, 2, 8));
            rmax = fmaxf(rmax, __shfl_xor_sync(0xffffffffu, rmax, 4, 8));
            const float mnew  = fmaxf(m_[i], rmax);
            const float alpha = __expf(m_[i] - mnew);
            float rsum = 0.f;
#pragma unroll
            for (int j = 0; j < 4; j++) {
                const float p = __expf(s_[i][j] - mnew);
                Ps[tm * 2 + i][tn * 4 + j] = p;
                rsum += p;
            }
            rsum += __shfl_xor_sync(0xffffffffu, rsum, 1, 8);
            rsum += __shfl_xor_sync(0xffffffffu, rsum, 2, 8);
            rsum += __shfl_xor_sync(0xffffffffu, rsum, 4, 8);
            l_[i] = l_[i] * alpha + rsum;
            m_[i] = mnew;
#pragma unroll
            for (int j = 0; j < 8; j++) o_[i][j] *= alpha;
        }
        __syncthreads();

#pragma unroll
        for (int kk = 0; kk < BKV; kk++) {
            const float p0 = Ps[tm * 2][kk];
            const float p1 = Ps[tm * 2 + 1][kk];
            const float4 v0 = *(const float4*)&Vs[kk][tn * 8];
            const float4 v1 = *(const float4*)&Vs[kk][tn * 8 + 4];
            o_[0][0] = fmaf(p0, v0.x, o_[0][0]);
            o_[0][1] = fmaf(p0, v0.y, o_[0][1]);
            o_[0][2] = fmaf(p0, v0.z, o_[0][2]);
            o_[0][3] = fmaf(p0, v0.w, o_[0][3]);
            o_[0][4] = fmaf(p0, v1.x, o_[0][4]);
            o_[0][5] = fmaf(p0, v1.y, o_[0][5]);
            o_[0][6] = fmaf(p0, v1.z, o_[0][6]);
            o_[0][7] = fmaf(p0, v1.w, o_[0][7]);
            o_[1][0] = fmaf(p1, v0.x, o_[1][0]);
            o_[1][1] = fmaf(p1, v0.y, o_[1][1]);
            o_[1][2] = fmaf(p1, v0.z, o_[1][2]);
            o_[1][3] = fmaf(p1, v0.w, o_[1][3]);
            o_[1][4] = fmaf(p1, v1.x, o_[1][4]);
            o_[1][5] = fmaf(p1, v1.y, o_[1][5]);
            o_[1][6] = fmaf(p1, v1.z, o_[1][6]);
            o_[1][7] = fmaf(p1, v1.w, o_[1][7]);
        }
        __syncthreads();
    }

#pragma unroll
    for (int i = 0; i < 2; i++) {
        const float inv = 1.f / l_[i];
        float* dst = att + ((size_t)(b * T_ + q0 + tm * 2 + i)) * C_ + h * D_ + tn * 8;
        *(float4*)dst       = make_float4(o_[i][0] * inv, o_[i][1] * inv,
                                          o_[i][2] * inv, o_[i][3] * inv);
        *(float4*)(dst + 4) = make_float4(o_[i][4] * inv, o_[i][5] * inv,
                                          o_[i][6] * inv, o_[i][7] * inv);
    }
}

// ---------------------------------------------------------------------------
extern "C" void kernel_launch(void* const* d_in, const int* in_sizes, int n_in,
                              void* d_out, int out_size)
{
    (void)in_sizes; (void)n_in; (void)out_size;
    const float* x     = (const float*)d_in[0];
    const float* wqkv  = (const float*)d_in[1];
    const float* wproj = (const float*)d_in[2];
    float* out = (float*)d_out;

    float *qkv, *att;
    __nv_bfloat16 *xh, *xl, *wqh, *wql, *ah, *al, *wph, *wpl;
    cudaGetSymbolAddress((void**)&qkv, g_qkv);
    cudaGetSymbolAddress((void**)&att, g_att);
    cudaGetSymbolAddress((void**)&xh,  s_xh);
    cudaGetSymbolAddress((void**)&xl,  s_xl);
    cudaGetSymbolAddress((void**)&wqh, s_wqh);
    cudaGetSymbolAddress((void**)&wql, s_wql);
    cudaGetSymbolAddress((void**)&ah,  s_ah);
    cudaGetSymbolAddress((void**)&al,  s_al);
    cudaGetSymbolAddress((void**)&wph, s_wph);
    cudaGetSymbolAddress((void**)&wpl, s_wpl);

    cudaFuncSetAttribute(gemm_bf16_split_kernel,
                         cudaFuncAttributeMaxDynamicSharedMemorySize, GEMM_SMEM);

    {
        int n2 = (M_ * C_) / 2;
        split_bf16_kernel<<<(n2 + 255) / 256, 256>>>(x, xh, xl, n2);
        int w2 = (QKVN * C_) / 2;
        split_bf16_kernel<<<(w2 + 255) / 256, 256>>>(wqkv, wqh, wql, w2);
    }
    gemm_bf16_split_kernel<<<dim3(QKVN / 128, M_ / 128), 256, GEMM_SMEM>>>(
        xh, xl, wqh, wql, qkv, QKVN);
    attn_kernel<<<dim3(T_ / 64, H_, B_), 256>>>(qkv, att);
    {
        int n2 = (M_ * C_) / 2;
        split_bf16_kernel<<<(n2 + 255) / 256, 256>>>(att, ah, al, n2);
        int w2 = (C_ * C_) / 2;
        split_bf16_kernel<<<(w2 + 255) / 256, 256>>>(wproj, wph, wpl, w2);
    }
    gemm_bf16_split_kernel<<<dim3(C_ / 128, M_ / 128), 256, GEMM_SMEM>>>(
        ah, al, wph, wpl, out, C_);
}

// round 4
// speedup vs baseline: 3.1485x; 2.3559x over previous
#include <cuda_runtime.h>
#include <cuda_bf16.h>
#include <math_constants.h>
#include <cstdint>

// Problem constants
#define B_    2
#define T_    2048
#define C_    1024
#define H_    16
#define D_    64
#define M_    (B_ * T_)      // 4096
#define QKVN  (3 * C_)       // 3072
#define K_    1024

// ---------------------------------------------------------------------------
// Device scratch
// ---------------------------------------------------------------------------
__device__ __nv_bfloat16 s_xh[(size_t)M_ * C_];
__device__ __nv_bfloat16 s_xl[(size_t)M_ * C_];
__device__ __nv_bfloat16 s_wqh[(size_t)QKVN * C_];
__device__ __nv_bfloat16 s_wql[(size_t)QKVN * C_];
__device__ __nv_bfloat16 s_qkvh[(size_t)M_ * QKVN];
__device__ __nv_bfloat16 s_qkvl[(size_t)M_ * QKVN];
__device__ __nv_bfloat16 s_ah[(size_t)M_ * C_];
__device__ __nv_bfloat16 s_al[(size_t)M_ * C_];
__device__ __nv_bfloat16 s_wph[(size_t)C_ * C_];
__device__ __nv_bfloat16 s_wpl[(size_t)C_ * C_];

// ---------------------------------------------------------------------------
// PTX helpers (portable: cp.async + ldmatrix + mma.sync only)
// ---------------------------------------------------------------------------
__device__ __forceinline__ uint32_t smem_u32(const void* p) {
    uint32_t a;
    asm("{ .reg .u64 t; cvta.to.shared.u64 t, %1; cvt.u32.u64 %0, t; }"
        : "=r"(a) : "l"(p));
    return a;
}

#define CP_ASYNC_16(dst, src) \
    asm volatile("cp.async.cg.shared.global [%0], [%1], 16;" \
                 :: "r"(dst), "l"(src) : "memory")
#define CP_ASYNC_COMMIT() asm volatile("cp.async.commit_group;" ::: "memory")
#define CP_ASYNC_WAIT_1() asm volatile("cp.async.wait_group 1;" ::: "memory")
#define CP_ASYNC_WAIT_0() asm volatile("cp.async.wait_group 0;" ::: "memory")

__device__ __forceinline__ void ldm_x4(uint32_t& r0, uint32_t& r1,
                                       uint32_t& r2, uint32_t& r3, uint32_t a) {
    asm volatile("ldmatrix.sync.aligned.m8n8.x4.shared.b16 {%0,%1,%2,%3}, [%4];"
                 : "=r"(r0), "=r"(r1), "=r"(r2), "=r"(r3) : "r"(a));
}

__device__ __forceinline__ void mma16816(float* c, const uint32_t* a,
                                         const uint32_t* b) {
    asm volatile(
        "mma.sync.aligned.m16n8k16.row.col.f32.bf16.bf16.f32 "
        "{%0,%1,%2,%3}, {%4,%5,%6,%7}, {%8,%9}, {%0,%1,%2,%3};"
        : "+f"(c[0]), "+f"(c[1]), "+f"(c[2]), "+f"(c[3])
        : "r"(a[0]), "r"(a[1]), "r"(a[2]), "r"(a[3]), "r"(b[0]), "r"(b[1]));
}

__device__ __forceinline__ void split2(float f0, float f1,
                                       uint32_t& hi, uint32_t& lo) {
    __nv_bfloat16 h0 = __float2bfloat16_rn(f0);
    __nv_bfloat16 h1 = __float2bfloat16_rn(f1);
    float l0 = f0 - __bfloat162float(h0);
    float l1 = f1 - __bfloat162float(h1);
    __nv_bfloat162 th; th.x = h0; th.y = h1;
    __nv_bfloat162 tl; tl.x = __float2bfloat16_rn(l0); tl.y = __float2bfloat16_rn(l1);
    hi = *(uint32_t*)&th;
    lo = *(uint32_t*)&tl;
}

// fast exp2: poly on FMA pipe instead of MUFU (error ~2.4e-6)
__device__ __forceinline__ float fexp2(float x) {
    x = fmaxf(x, -120.f);
    int ni = __float2int_rn(x);
    float f = x - (float)ni;
    float p =          1.3333558146e-3f;
    p = fmaf(p, f, 9.6181291076e-3f);
    p = fmaf(p, f, 5.5504108664e-2f);
    p = fmaf(p, f, 2.4022650696e-1f);
    p = fmaf(p, f, 6.9314718056e-1f);
    p = fmaf(p, f, 1.0f);
    return __int_as_float((ni + 127) << 23) * p;
}

// ---------------------------------------------------------------------------
// bf16 hi/lo split of an fp32 buffer
// ---------------------------------------------------------------------------
__global__ __launch_bounds__(256)
void split_bf16_kernel(const float* __restrict__ in,
                       __nv_bfloat16* __restrict__ hi,
                       __nv_bfloat16* __restrict__ lo, int n2)
{
    int i = blockIdx.x * blockDim.x + threadIdx.x;
    if (i >= n2) return;
    float2 v = ((const float2*)in)[i];
    uint32_t h, l;
    split2(v.x, v.y, h, l);
    ((uint32_t*)hi)[i] = h;
    ((uint32_t*)lo)[i] = l;
}

// ---------------------------------------------------------------------------
// mma.sync bf16 split-GEMM: C[M,N] = (Ah+Al)[M,K] @ (Bh+Bl)[N,K]^T, 3 passes.
// Output either fp32 (Cm) or bf16 hi/lo split (Oh/Ol).
// ---------------------------------------------------------------------------
#define KT_   (K_ / 64)
#define NIT_  (3 * KT_)
#define TILEB 16384
#define GEMM_SMEM (4 * TILEB + 128)

__device__ __forceinline__ void issue_tile_load(
    int L,
    const __nv_bfloat16* __restrict__ Ah, const __nv_bfloat16* __restrict__ Al,
    const __nv_bfloat16* __restrict__ Bh, const __nv_bfloat16* __restrict__ Bl,
    uint32_t sA, uint32_t sB, int m0, int n0, int tid)
{
    const int p  = L >> 4;
    const int kt = L & 15;
    const __nv_bfloat16* A = (p == 1) ? Al : Ah;
    const __nv_bfloat16* B = (p == 2) ? Bl : Bh;
    const int r0 = tid >> 3;
    const int ch = tid & 7;
    const uint32_t cb = (uint32_t)ch * 16u;
#pragma unroll
    for (int q = 0; q < 4; q++) {
        const int row = r0 + q * 32;
        const uint32_t sw = (uint32_t)row * 128u + (cb ^ (((uint32_t)row & 7u) << 4));
        CP_ASYNC_16(sA + sw, A + (size_t)(m0 + row) * K_ + kt * 64 + ch * 8);
        CP_ASYNC_16(sB + sw, B + (size_t)(n0 + row) * K_ + kt * 64 + ch * 8);
    }
    CP_ASYNC_COMMIT();
}

template<bool SPLIT_OUT>
__global__ __launch_bounds__(256)
void gemm_bf16_split_kernel(const __nv_bfloat16* __restrict__ Ah,
                            const __nv_bfloat16* __restrict__ Al,
                            const __nv_bfloat16* __restrict__ Bh,
                            const __nv_bfloat16* __restrict__ Bl,
                            float* __restrict__ Cm,
                            __nv_bfloat16* __restrict__ Oh,
                            __nv_bfloat16* __restrict__ Ol, int N)
{
    extern __shared__ char dsm[];
    const uint32_t base = (smem_u32(dsm) + 127u) & ~127u;

    const int tid  = threadIdx.x;
    const int wid  = tid >> 5;
    const int lane = tid & 31;
    const int wm   = wid >> 2;
    const int wn   = wid & 3;
    const int m0 = blockIdx.y * 128;
    const int n0 = blockIdx.x * 128;

    const uint32_t sA[2] = { base,         base + 2 * TILEB };
    const uint32_t sB[2] = { base + TILEB, base + 3 * TILEB };

    float acc[4][4][4];
#pragma unroll
    for (int i = 0; i < 4; i++)
#pragma unroll
        for (int j = 0; j < 4; j++)
#pragma unroll
            for (int q = 0; q < 4; q++) acc[i][j][q] = 0.f;

    const int lr = lane & 15;
    const uint32_t lc = ((uint32_t)(lane >> 4)) << 4;

    issue_tile_load(0, Ah, Al, Bh, Bl, sA[0], sB[0], m0, n0, tid);
    issue_tile_load(1, Ah, Al, Bh, Bl, sA[1], sB[1], m0, n0, tid);

    for (int it = 0; it < NIT_; ++it) {
        const int s = it & 1;
        if (it + 2 < NIT_) { CP_ASYNC_WAIT_1(); } else { CP_ASYNC_WAIT_0(); }
        __syncthreads();

#pragma unroll
        for (int kk = 0; kk < 4; kk++) {
            const uint32_t colb = (uint32_t)kk * 32u + lc;
            uint32_t a[4][4];
#pragma unroll
            for (int mi = 0; mi < 4; mi++) {
                const int row = wm * 64 + mi * 16 + lr;
                const uint32_t ad = sA[s] + (uint32_t)row * 128u +
                                    (colb ^ (((uint32_t)row & 7u) << 4));
                ldm_x4(a[mi][0], a[mi][1], a[mi][2], a[mi][3], ad);
            }
            uint32_t b[4][2];
#pragma unroll
            for (int bj = 0; bj < 2; bj++) {
                const int row = wn * 32 + bj * 16 + lr;
                const uint32_t ad = sB[s] + (uint32_t)row * 128u +
                                    (colb ^ (((uint32_t)row & 7u) << 4));
                uint32_t r0, r1, r2, r3;
                ldm_x4(r0, r1, r2, r3, ad);
                b[bj * 2 + 0][0] = r0; b[bj * 2 + 1][0] = r1;
                b[bj * 2 + 0][1] = r2; b[bj * 2 + 1][1] = r3;
            }
#pragma unroll
            for (int mi = 0; mi < 4; mi++)
#pragma unroll
                for (int ni = 0; ni < 4; ni++)
                    mma16816(acc[mi][ni], a[mi], b[ni]);
        }
        __syncthreads();

        if (it + 2 < NIT_)
            issue_tile_load(it + 2, Ah, Al, Bh, Bl, sA[s], sB[s], m0, n0, tid);
    }

    const int rr = lane >> 2;
    const int cc = (lane & 3) * 2;
#pragma unroll
    for (int mi = 0; mi < 4; mi++) {
#pragma unroll
        for (int ni = 0; ni < 4; ni++) {
            const int gm = m0 + wm * 64 + mi * 16 + rr;
            const int gn = n0 + wn * 32 + ni * 8 + cc;
            if (!SPLIT_OUT) {
                *(float2*)(Cm + (size_t)gm * N + gn) =
                    make_float2(acc[mi][ni][0], acc[mi][ni][1]);
                *(float2*)(Cm + (size_t)(gm + 8) * N + gn) =
                    make_float2(acc[mi][ni][2], acc[mi][ni][3]);
            } else {
                uint32_t h, l;
                split2(acc[mi][ni][0], acc[mi][ni][1], h, l);
                *(uint32_t*)(Oh + (size_t)gm * N + gn) = h;
                *(uint32_t*)(Ol + (size_t)gm * N + gn) = l;
                split2(acc[mi][ni][2], acc[mi][ni][3], h, l);
                *(uint32_t*)(Oh + (size_t)(gm + 8) * N + gn) = h;
                *(uint32_t*)(Ol + (size_t)(gm + 8) * N + gn) = l;
            }
        }
    }
}

// ---------------------------------------------------------------------------
// Tensor-core flash attention (causal), bf16 hi/lo split, poly-exp2 softmax.
// CTA: 256 thr = 8 warps, BQ=128 (16 q rows/warp), BKV=64, D=64.
// Outputs bf16 hi/lo directly for the proj GEMM.
// ---------------------------------------------------------------------------
#define BQ_   128
#define BKV_  64
// smem offsets (bytes, from 1024-aligned base)
#define AQH   0u
#define AQL   16384u
#define AVTH  0u          // reuse Q region after fragments loaded
#define AVTL  8192u
#define AKST  32768u      // + s*16384 : Kh +0, Kl +8192
#define AVST  65536u      // + s*16384 : Vh +0, Vl +8192
#define ATTN_SMEM (98304 + 1024)

__global__ __launch_bounds__(256, 1)
void attn_mma_kernel(const __nv_bfloat16* __restrict__ qh_g,
                     const __nv_bfloat16* __restrict__ ql_g,
                     __nv_bfloat16* __restrict__ oh_g,
                     __nv_bfloat16* __restrict__ ol_g)
{
    extern __shared__ char dsm[];
    char* sm = (char*)(((uintptr_t)dsm + 1023) & ~(uintptr_t)1023);
    const uint32_t smb = smem_u32(sm);

    const int qb = (int)gridDim.x - 1 - (int)blockIdx.x;  // big work first
    const int h  = blockIdx.y, b = blockIdx.z;
    const int q0 = qb * BQ_;
    const int tid  = threadIdx.x;
    const int w    = tid >> 5;
    const int lane = tid & 31;
    const int lr   = lane & 15;
    const uint32_t lc = ((uint32_t)(lane >> 4)) << 4;
    const float SC = 0.18033688011f;   // (1/8) * log2(e)

    // ---- prologue: Q tile (hi+lo) via cp.async ----
    {
        const int r  = tid >> 1;
        const int cb = (tid & 1) * 4;
        const size_t grow = (size_t)(b * T_ + q0 + r) * QKVN + h * D_;
#pragma unroll
        for (int c = 0; c < 4; c++) {
            const uint32_t off = (uint32_t)r * 128u +
                (((uint32_t)(cb + c) * 16u) ^ (((uint32_t)r & 7u) << 4));
            CP_ASYNC_16(smb + AQH + off, qh_g + grow + (cb + c) * 8);
            CP_ASYNC_16(smb + AQL + off, ql_g + grow + (cb + c) * 8);
        }
        CP_ASYNC_COMMIT();
    }

    // KV tile loader (K and V, hi and lo) into stage s
    auto issue_kv = [&](int kt, int s) {
        const int r  = tid >> 2;
        const int c0 = tid & 3;
        const size_t krow = (size_t)(b * T_ + kt * BKV_ + r) * QKVN + h * D_;
        const uint32_t ks = smb + AKST + (uint32_t)s * 16384u;
        const uint32_t vs = smb + AVST + (uint32_t)s * 16384u;
#pragma unroll
        for (int q = 0; q < 2; q++) {
            const int c = c0 + q * 4;
            const uint32_t off = (uint32_t)r * 128u +
                (((uint32_t)c * 16u) ^ (((uint32_t)r & 7u) << 4));
            CP_ASYNC_16(ks + off,         qh_g + krow + C_     + c * 8);
            CP_ASYNC_16(ks + 8192u + off, ql_g + krow + C_     + c * 8);
            CP_ASYNC_16(vs + off,         qh_g + krow + 2 * C_ + c * 8);
            CP_ASYNC_16(vs + 8192u + off, ql_g + krow + 2 * C_ + c * 8);
        }
        CP_ASYNC_COMMIT();
    };

    issue_kv(0, 0);
    CP_ASYNC_WAIT_1();      // Q group done
    __syncthreads();

    // ---- Q fragments into registers (then Q smem region becomes Vt) ----
    uint32_t qhf[4][4], qlf[4][4];
#pragma unroll
    for (int kk = 0; kk < 4; kk++) {
        const int row = w * 16 + lr;
        const uint32_t colb = (uint32_t)kk * 32u + lc;
        const uint32_t sw = (uint32_t)row * 128u +
                            (colb ^ (((uint32_t)row & 7u) << 4));
        ldm_x4(qhf[kk][0], qhf[kk][1], qhf[kk][2], qhf[kk][3], smb + AQH + sw);
        ldm_x4(qlf[kk][0], qlf[kk][1], qlf[kk][2], qlf[kk][3], smb + AQL + sw);
    }

    float acco[8][4];
#pragma unroll
    for (int j = 0; j < 8; j++)
#pragma unroll
        for (int q = 0; q < 4; q++) acco[j][q] = 0.f;
    float m_[2] = { -1e30f, -1e30f };
    float l_[2] = { 0.f, 0.f };

    const int nkb = 2 * qb + 2;
    for (int kt = 0; kt < nkb; kt++) {
        const int s  = kt & 1;
        const int k0 = kt * BKV_;
        CP_ASYNC_WAIT_0();
        __syncthreads();                         // tile kt ready; all PV(kt-1) done
        if (kt + 1 < nkb) issue_kv(kt + 1, s ^ 1);

        const uint32_t ks = smb + AKST + (uint32_t)s * 16384u;

        // ---- S = Q @ K^T (3-pass split) ----
        float accs[8][4];
#pragma unroll
        for (int j = 0; j < 8; j++)
#pragma unroll
            for (int q = 0; q < 4; q++) accs[j][q] = 0.f;

#pragma unroll
        for (int kk = 0; kk < 4; kk++) {
            uint32_t bh[8][2], bl[8][2];
#pragma unroll
            for (int bj = 0; bj < 4; bj++) {
                const int row = bj * 16 + lr;
                const uint32_t colb = (uint32_t)kk * 32u + lc;
                const uint32_t ad = ks + (uint32_t)row * 128u +
                                    (colb ^ (((uint32_t)row & 7u) << 4));
                uint32_t r0, r1, r2, r3;
                ldm_x4(r0, r1, r2, r3, ad);
                bh[bj*2][0]=r0; bh[bj*2+1][0]=r1; bh[bj*2][1]=r2; bh[bj*2+1][1]=r3;
                ldm_x4(r0, r1, r2, r3, ad + 8192u);
                bl[bj*2][0]=r0; bl[bj*2+1][0]=r1; bl[bj*2][1]=r2; bl[bj*2+1][1]=r3;
            }
#pragma unroll
            for (int j = 0; j < 8; j++) {
                mma16816(accs[j], qhf[kk], bh[j]);
                mma16816(accs[j], qlf[kk], bh[j]);
                mma16816(accs[j], qhf[kk], bl[j]);
            }
        }

        // ---- causal mask + online softmax (poly exp2) ----
        const int qg_base = q0 + w * 16 + (lane >> 2);
#pragma unroll
        for (int pp = 0; pp < 2; pp++) {
            const int qg = qg_base + 8 * pp;
            float mx = m_[pp];
#pragma unroll
            for (int j = 0; j < 8; j++) {
                const int kg = k0 + j * 8 + (lane & 3) * 2;
                float v0 = (kg     <= qg) ? accs[j][2*pp  ] * SC : -1e30f;
                float v1 = (kg + 1 <= qg) ? accs[j][2*pp+1] * SC : -1e30f;
                accs[j][2*pp] = v0; accs[j][2*pp+1] = v1;
                mx = fmaxf(mx, fmaxf(v0, v1));
            }
            mx = fmaxf(mx, __shfl_xor_sync(0xffffffffu, mx, 1));
            mx = fmaxf(mx, __shfl_xor_sync(0xffffffffu, mx, 2));
            const float alpha = fexp2(m_[pp] - mx);
            float rs = 0.f;
#pragma unroll
            for (int j = 0; j < 8; j++) {
                const float p0 = fexp2(accs[j][2*pp  ] - mx);
                const float p1 = fexp2(accs[j][2*pp+1] - mx);
                accs[j][2*pp] = p0; accs[j][2*pp+1] = p1;
                rs += p0 + p1;
            }
            rs += __shfl_xor_sync(0xffffffffu, rs, 1);
            rs += __shfl_xor_sync(0xffffffffu, rs, 2);
            l_[pp] = l_[pp] * alpha + rs;
            m_[pp] = mx;
#pragma unroll
            for (int j = 0; j < 8; j++) {
                acco[j][2*pp] *= alpha; acco[j][2*pp+1] *= alpha;
            }
        }

        // ---- pack P (hi/lo) into A fragments, registers only ----
        uint32_t ph[4][4], pl[4][4];
#pragma unroll
        for (int t = 0; t < 4; t++) {
            split2(accs[2*t  ][0], accs[2*t  ][1], ph[t][0], pl[t][0]);
            split2(accs[2*t  ][2], accs[2*t  ][3], ph[t][1], pl[t][1]);
            split2(accs[2*t+1][0], accs[2*t+1][1], ph[t][2], pl[t][2]);
            split2(accs[2*t+1][2], accs[2*t+1][3], ph[t][3], pl[t][3]);
        }

        // ---- transpose V (natural smem -> Vt smem, bank-rotated) ----
        {
            const int kvp = tid >> 3;
            const int c   = tid & 7;
            const int kv0 = kvp * 2;
            const uint32_t vs = AVST + (uint32_t)s * 16384u;
            const uint32_t offA = (uint32_t)kv0 * 128u +
                (((uint32_t)c * 16u) ^ (((uint32_t)kv0 & 7u) << 4));
            const uint32_t offB = (uint32_t)(kv0+1) * 128u +
                (((uint32_t)c * 16u) ^ (((uint32_t)(kv0+1) & 7u) << 4));
            uint4 vh0 = *(const uint4*)(sm + vs + offA);
            uint4 vh1 = *(const uint4*)(sm + vs + offB);
            uint4 vl0 = *(const uint4*)(sm + vs + 8192u + offA);
            uint4 vl1 = *(const uint4*)(sm + vs + 8192u + offB);
            const __nv_bfloat16* h0b = (const __nv_bfloat16*)&vh0;
            const __nv_bfloat16* h1b = (const __nv_bfloat16*)&vh1;
            const __nv_bfloat16* l0b = (const __nv_bfloat16*)&vl0;
            const __nv_bfloat16* l1b = (const __nv_bfloat16*)&vl1;
#pragma unroll
            for (int ii = 0; ii < 8; ii++) {
                const int i = (ii + c) & 7;
                const int d = c * 8 + i;
                const uint32_t so = (uint32_t)d * 128u +
                    (((uint32_t)kv0 * 2u) ^ ((uint32_t)i << 4));
                __nv_bfloat162 th; th.x = h0b[i]; th.y = h1b[i];
                __nv_bfloat162 tl; tl.x = l0b[i]; tl.y = l1b[i];
                *(uint32_t*)(sm + AVTH + so) = *(uint32_t*)&th;
                *(uint32_t*)(sm + AVTL + so) = *(uint32_t*)&tl;
            }
        }
        __syncthreads();

        // ---- O += P @ V (3-pass split), B frags from Vt ----
#pragma unroll
        for (int kk = 0; kk < 4; kk++) {
            uint32_t bvh[8][2], bvl[8][2];
#pragma unroll
            for (int bj = 0; bj < 4; bj++) {
                const int row = bj * 16 + lr;
                const uint32_t colb = (uint32_t)kk * 32u + lc;
                const uint32_t sw = (uint32_t)row * 128u +
                                    (colb ^ (((uint32_t)row & 7u) << 4));
                uint32_t r0, r1, r2, r3;
                ldm_x4(r0, r1, r2, r3, smb + AVTH + sw);
                bvh[bj*2][0]=r0; bvh[bj*2+1][0]=r1; bvh[bj*2][1]=r2; bvh[bj*2+1][1]=r3;
                ldm_x4(r0, r1, r2, r3, smb + AVTL + sw);
                bvl[bj*2][0]=r0; bvl[bj*2+1][0]=r1; bvl[bj*2][1]=r2; bvl[bj*2+1][1]=r3;
            }
#pragma unroll
            for (int j = 0; j < 8; j++) {
                mma16816(acco[j], ph[kk], bvh[j]);
                mma16816(acco[j], pl[kk], bvh[j]);
                mma16816(acco[j], ph[kk], bvl[j]);
            }
        }
    }

    // ---- epilogue: normalize, split to bf16 hi/lo, write [B*T, C] ----
#pragma unroll
    for (int pp = 0; pp < 2; pp++) {
        const float inv = 1.f / l_[pp];
        const size_t row = (size_t)(b * T_ + q0 + w * 16 + (lane >> 2) + 8 * pp);
#pragma unroll
        for (int j = 0; j < 8; j++) {
            const int dcol = h * D_ + j * 8 + (lane & 3) * 2;
            uint32_t hbits, lbits;
            split2(acco[j][2*pp] * inv, acco[j][2*pp+1] * inv, hbits, lbits);
            *(uint32_t*)(oh_g + row * C_ + dcol) = hbits;
            *(uint32_t*)(ol_g + row * C_ + dcol) = lbits;
        }
    }
}

// ---------------------------------------------------------------------------
extern "C" void kernel_launch(void* const* d_in, const int* in_sizes, int n_in,
                              void* d_out, int out_size)
{
    (void)in_sizes; (void)n_in; (void)out_size;
    const float* x     = (const float*)d_in[0];
    const float* wqkv  = (const float*)d_in[1];
    const float* wproj = (const float*)d_in[2];
    float* out = (float*)d_out;

    __nv_bfloat16 *xh, *xl, *wqh, *wql, *qkvh, *qkvl, *ah, *al, *wph, *wpl;
    cudaGetSymbolAddress((void**)&xh,   s_xh);
    cudaGetSymbolAddress((void**)&xl,   s_xl);
    cudaGetSymbolAddress((void**)&wqh,  s_wqh);
    cudaGetSymbolAddress((void**)&wql,  s_wql);
    cudaGetSymbolAddress((void**)&qkvh, s_qkvh);
    cudaGetSymbolAddress((void**)&qkvl, s_qkvl);
    cudaGetSymbolAddress((void**)&ah,   s_ah);
    cudaGetSymbolAddress((void**)&al,   s_al);
    cudaGetSymbolAddress((void**)&wph,  s_wph);
    cudaGetSymbolAddress((void**)&wpl,  s_wpl);

    cudaFuncSetAttribute(gemm_bf16_split_kernel<true>,
                         cudaFuncAttributeMaxDynamicSharedMemorySize, GEMM_SMEM);
    cudaFuncSetAttribute(gemm_bf16_split_kernel<false>,
                         cudaFuncAttributeMaxDynamicSharedMemorySize, GEMM_SMEM);
    cudaFuncSetAttribute(attn_mma_kernel,
                         cudaFuncAttributeMaxDynamicSharedMemorySize, ATTN_SMEM);

    // 1) split inputs
    {
        int n2 = (M_ * C_) / 2;
        split_bf16_kernel<<<(n2 + 255) / 256, 256>>>(x, xh, xl, n2);
        int w2 = (QKVN * C_) / 2;
        split_bf16_kernel<<<(w2 + 255) / 256, 256>>>(wqkv, wqh, wql, w2);
        int p2 = (C_ * C_) / 2;
        split_bf16_kernel<<<(p2 + 255) / 256, 256>>>(wproj, wph, wpl, p2);
    }
    // 2) QKV projection -> bf16 hi/lo directly
    gemm_bf16_split_kernel<true><<<dim3(QKVN / 128, M_ / 128), 256, GEMM_SMEM>>>(
        xh, xl, wqh, wql, nullptr, qkvh, qkvl, QKVN);
    // 3) tensor-core causal flash attention -> bf16 hi/lo
    attn_mma_kernel<<<dim3(T_ / BQ_, H_, B_), 256, ATTN_SMEM>>>(qkvh, qkvl, ah, al);
    // 4) output projection -> fp32
    gemm_bf16_split_kernel<false><<<dim3(C_ / 128, M_ / 128), 256, GEMM_SMEM>>>(
        ah, al, wph, wpl, out, nullptr, nullptr, C_);
}